// round 5
// baseline (speedup 1.0000x reference)
#include <cuda_runtime.h>

#define NN 50000
#define EE 500000
#define HH 128
// per-node feature block = 4 channels * 128 = 512 floats

// ---- scratch (static __device__ arrays; no runtime allocation) ----
__device__ int   g_cnt[NN];
__device__ int   g_off[NN + 1];
__device__ int   g_cur[NN];
__device__ int   g_cols[EE];
__device__ int   g_is32;                    // 1 if edge_index buffer is int32
__device__ float g_agg[(size_t)NN * 512];   // aggregated raw features, layout == x

#define FFMA2(d, a, b) \
    asm("fma.rn.f32x2 %0, %1, %2, %0;" : "+l"(d) : "l"(a), "l"(b))

// ---------------- dtype detection + zero (fused) ----------------
__global__ void k_init() {
    int i = blockIdx.x * blockDim.x + threadIdx.x;
    if (i == 0) g_is32 = 0;
    if (i < NN) g_cnt[i] = 0;
}

// Interpret first EE elements as int64. That spans exactly 2*EE int32 words
// (the whole buffer if it is int32), so the read is in-bounds either way.
__global__ void k_dtype_detect(const long long* __restrict__ ei) {
    int e = blockIdx.x * blockDim.x + threadIdx.x;
    if (e < EE) {
        long long v = ei[e];
        if (v < 0 || v >= NN) atomicOr(&g_is32, 1);
    }
}

__device__ __forceinline__ int load_idx(const void* ei, int pos, int is32) {
    long long v;
    if (is32) v = ((const int*)ei)[pos];
    else      v = ((const long long*)ei)[pos];
    int r = (int)v;
    if (r < 0) r = 0;
    if (r >= NN) r = NN - 1;
    return r;
}

// ---------------- CSR build ----------------
__global__ void k_hist(const void* __restrict__ ei) {
    int e = blockIdx.x * blockDim.x + threadIdx.x;
    if (e < EE) {
        int is32 = g_is32;
        int r = load_idx(ei, e, is32);
        atomicAdd(&g_cnt[r], 1);
    }
}

__global__ void k_scan() {
    __shared__ int part[1024];
    int t = threadIdx.x;
    const int CH = (NN + 1023) / 1024;
    int beg = t * CH;
    int end = beg + CH; if (end > NN) end = NN;
    int s = 0;
    for (int i = beg; i < end; i++) s += g_cnt[i];
    part[t] = s;
    __syncthreads();
    for (int d = 1; d < 1024; d <<= 1) {
        int v = (t >= d) ? part[t - d] : 0;
        __syncthreads();
        part[t] += v;
        __syncthreads();
    }
    int run = (t == 0) ? 0 : part[t - 1];
    for (int i = beg; i < end; i++) {
        int c = g_cnt[i];
        g_off[i] = run;
        g_cur[i] = run;
        run += c;
    }
    if (t == 1023) g_off[NN] = EE;
}

__global__ void k_fill(const void* __restrict__ ei) {
    int e = blockIdx.x * blockDim.x + threadIdx.x;
    if (e < EE) {
        int is32 = g_is32;
        int r = load_idx(ei, e, is32);
        int c = load_idx(ei, EE + e, is32);
        int p = atomicAdd(&g_cur[r], 1);
        g_cols[p] = c;
    }
}

// ---------------- aggregate raw features: agg[n] = sum_{e: row=n} x[col_e] ----------------
__global__ void __launch_bounds__(128) k_agg(const float4* __restrict__ xv) {
    int n = blockIdx.x;
    int t = threadIdx.x;
    int beg = g_off[n], end = g_off[n + 1];
    float4 acc = make_float4(0.f, 0.f, 0.f, 0.f);
    int j = beg;
    for (; j + 3 < end; j += 4) {
        int c0 = g_cols[j], c1 = g_cols[j + 1], c2 = g_cols[j + 2], c3 = g_cols[j + 3];
        float4 v0 = xv[(size_t)c0 * 128 + t];
        float4 v1 = xv[(size_t)c1 * 128 + t];
        float4 v2 = xv[(size_t)c2 * 128 + t];
        float4 v3 = xv[(size_t)c3 * 128 + t];
        acc.x += v0.x + v1.x + v2.x + v3.x;
        acc.y += v0.y + v1.y + v2.y + v3.y;
        acc.z += v0.z + v1.z + v2.z + v3.z;
        acc.w += v0.w + v1.w + v2.w + v3.w;
    }
    for (; j < end; j++) {
        int c0 = g_cols[j];
        float4 v0 = xv[(size_t)c0 * 128 + t];
        acc.x += v0.x; acc.y += v0.y; acc.z += v0.z; acc.w += v0.w;
    }
    ((float4*)g_agg)[(size_t)n * 128 + t] = acc;
}

// ---------------- fused GEMM: out_row = [x_row | agg_row] @ [Wroot | Wrel].T (+bias) ----------------
// 128x128 tile, K=256 in 8-wide chunks, double-buffered, FFMA2 micro-kernel.
// Micro-tile per thread: 8 rows x 4 column-pairs. As stored duplicated (a,a) as u64.
template <int MODE, bool BIAS>
__global__ void __launch_bounds__(256, 2) k_gemm(const float* __restrict__ X,
                                                 const float* __restrict__ Wroot,
                                                 const float* __restrict__ Wrel,
                                                 const float* __restrict__ bias,
                                                 float* __restrict__ out, int M) {
    __shared__ unsigned long long AsD[2][8][128];   // duplicated (a,a) pairs
    __shared__ float Bs[2][8][128];
    __shared__ int   roff[128];

    int tid = threadIdx.x;
    int mbase = blockIdx.x * 128;

    if (tid < 128) {
        int m = mbase + tid;
        if (m >= M) m = M - 1;          // clamp: duplicate loads, stores guarded later
        int off;
        if (MODE == 0) {
            off = m * 512;
        } else {
            int n = m / 3;
            int c = 1 + (m % 3);
            off = n * 512 + c * 128;
        }
        roff[tid] = off;
    }
    __syncthreads();

    unsigned long long acc[8][4];
#pragma unroll
    for (int i = 0; i < 8; i++)
#pragma unroll
        for (int j = 0; j < 4; j++) acc[i][j] = 0ull;

    int lr  = tid >> 1;          // 0..127 : row (A) / output (B) index
    int lkq = (tid & 1) * 4;     // 0 or 4 : which float4 of the 8-wide k-chunk
    int tm  = tid >> 4;          // 0..15 -> rows tm*8..+7
    int tn  = tid & 15;          // 0..15 -> cols tn*8..+7

    const float* Agg = g_agg;
    int arow = roff[lr];

    // chunk fetch helper (registers)
    float4 av, bv;
    {   // prologue: chunk 0
        av = *(const float4*)(X + arow + lkq);
        bv = *(const float4*)(Wroot + lr * 128 + lkq);
#pragma unroll
        for (int q = 0; q < 4; q++) {
            float a = (&av.x)[q];
            float2 dup = make_float2(a, a);
            AsD[0][lkq + q][lr] = *(unsigned long long*)&dup;
            Bs[0][lkq + q][lr]  = (&bv.x)[q];
        }
    }
    __syncthreads();

#pragma unroll 1
    for (int kc = 0; kc < 32; kc++) {
        int cur = kc & 1;

        if (kc < 31) {  // prefetch next chunk from global
            int k0 = (kc + 1) * 8;
            bool fh = (k0 < 128);
            int  kk = fh ? k0 : (k0 - 128);
            const float* srcA = fh ? X : Agg;
            const float* srcB = fh ? Wroot : Wrel;
            av = *(const float4*)(srcA + arow + kk + lkq);
            bv = *(const float4*)(srcB + lr * 128 + kk + lkq);
        }

#pragma unroll
        for (int p = 0; p < 8; p++) {
            const ulonglong2* ad = (const ulonglong2*)&AsD[cur][p][tm * 8];
            ulonglong2 a01 = ad[0], a23 = ad[1], a45 = ad[2], a67 = ad[3];
            const ulonglong2* bd = (const ulonglong2*)&Bs[cur][p][tn * 8];
            ulonglong2 b01 = bd[0], b23 = bd[1];
            unsigned long long ar[8] = {a01.x, a01.y, a23.x, a23.y,
                                        a45.x, a45.y, a67.x, a67.y};
            unsigned long long br[4] = {b01.x, b01.y, b23.x, b23.y};
#pragma unroll
            for (int i = 0; i < 8; i++) {
#pragma unroll
                for (int j = 0; j < 4; j++) {
                    FFMA2(acc[i][j], ar[i], br[j]);
                }
            }
        }

        if (kc < 31) {
            int nxt = cur ^ 1;
#pragma unroll
            for (int q = 0; q < 4; q++) {
                float a = (&av.x)[q];
                float2 dup = make_float2(a, a);
                AsD[nxt][lkq + q][lr] = *(unsigned long long*)&dup;
                Bs[nxt][lkq + q][lr]  = (&bv.x)[q];
            }
            __syncthreads();
        }
    }

    // epilogue
    float bs[8];
#pragma unroll
    for (int j = 0; j < 8; j++) bs[j] = BIAS ? bias[tn * 8 + j] : 0.f;

    __syncthreads();   // smem hygiene before exit; roff unchanged

#pragma unroll
    for (int i = 0; i < 8; i++) {
        int lm = tm * 8 + i;
        int m  = mbase + lm;
        if (m < M) {
            float* o = out + roff[lm] + tn * 8;
            float2 p0 = *(float2*)&acc[i][0];
            float2 p1 = *(float2*)&acc[i][1];
            float2 p2 = *(float2*)&acc[i][2];
            float2 p3 = *(float2*)&acc[i][3];
            float4 v0, v1;
            v0.x = p0.x + bs[0]; v0.y = p0.y + bs[1];
            v0.z = p1.x + bs[2]; v0.w = p1.y + bs[3];
            v1.x = p2.x + bs[4]; v1.y = p2.y + bs[5];
            v1.z = p3.x + bs[6]; v1.w = p3.y + bs[7];
            *(float4*)(o)     = v0;
            *(float4*)(o + 4) = v1;
        }
    }
}

extern "C" void kernel_launch(void* const* d_in, const int* in_sizes, int n_in,
                              void* d_out, int out_size) {
    const float* x        = (const float*)d_in[0];
    const void*  ei       = d_in[1];
    const float* W_s_rel  = (const float*)d_in[2];
    const float* W_s_root = (const float*)d_in[3];
    const float* b_s_root = (const float*)d_in[4];
    const float* W_v_rel  = (const float*)d_in[5];
    const float* W_v_root = (const float*)d_in[6];
    float*       out      = (float*)d_out;

    k_init<<<(NN + 255) / 256, 256>>>();
    k_dtype_detect<<<(EE + 255) / 256, 256>>>((const long long*)ei);
    k_hist<<<(EE + 255) / 256, 256>>>(ei);
    k_scan<<<1, 1024>>>();
    k_fill<<<(EE + 255) / 256, 256>>>(ei);
    k_agg<<<NN, 128>>>((const float4*)x);

    // scalar channel: out[:,0,:] = x_s @ Ws_root.T + b + agg_s @ Ws_rel.T
    k_gemm<0, true><<<(NN + 127) / 128, 256>>>(x, W_s_root, W_s_rel, b_s_root, out, NN);
    // vector channels: out[:,1:,:] = x_v @ Wv_root.T + agg_v @ Wv_rel.T
    k_gemm<1, false><<<(3 * NN + 127) / 128, 256>>>(x, W_v_root, W_v_rel, nullptr, out, 3 * NN);
}

// round 6
// speedup vs baseline: 1.2229x; 1.2229x over previous
#include <cuda_runtime.h>

#define NN 50000
#define EE 500000
#define HH 128
#define SCAN_NB 196   // ceil(50000/256)

// ---- scratch (static __device__ arrays; no runtime allocation) ----
__device__ int   g_cnt[NN];
__device__ int   g_off[NN + 1];
__device__ int   g_cur[NN];
__device__ int   g_cols[EE];
__device__ int   g_blksum[SCAN_NB];
__device__ int   g_is32;                    // 1 if edge_index buffer is int32
__device__ float g_agg[(size_t)NN * 512];   // aggregated raw features, layout == x

// ---------------- dtype detection + zero (fused) ----------------
__global__ void k_init() {
    int i = blockIdx.x * blockDim.x + threadIdx.x;
    if (i == 0) g_is32 = 0;
    if (i < NN) g_cnt[i] = 0;
}

// Interpret first EE elements as int64. That spans exactly 2*EE int32 words
// (the whole buffer if it is int32), so the read is in-bounds either way.
__global__ void k_dtype_detect(const long long* __restrict__ ei) {
    int e = blockIdx.x * blockDim.x + threadIdx.x;
    if (e < EE) {
        long long v = ei[e];
        if (v < 0 || v >= NN) atomicOr(&g_is32, 1);
    }
}

__device__ __forceinline__ int load_idx(const void* ei, int pos, int is32) {
    long long v;
    if (is32) v = ((const int*)ei)[pos];
    else      v = ((const long long*)ei)[pos];
    int r = (int)v;
    if (r < 0) r = 0;
    if (r >= NN) r = NN - 1;
    return r;
}

// ---------------- CSR build ----------------
__global__ void k_hist(const void* __restrict__ ei) {
    int e = blockIdx.x * blockDim.x + threadIdx.x;
    if (e < EE) {
        int is32 = g_is32;
        int r = load_idx(ei, e, is32);
        atomicAdd(&g_cnt[r], 1);
    }
}

// ---- 3-phase parallel exclusive scan of g_cnt into g_off/g_cur ----
// Phase 1: per-block inclusive scan; store local EXCLUSIVE prefix in g_off,
//          block total in g_blksum.
__global__ void __launch_bounds__(256) k_scan1() {
    __shared__ int s[256];
    int t = threadIdx.x;
    int i = blockIdx.x * 256 + t;
    int v = (i < NN) ? g_cnt[i] : 0;
    s[t] = v;
    __syncthreads();
#pragma unroll
    for (int d = 1; d < 256; d <<= 1) {
        int u = (t >= d) ? s[t - d] : 0;
        __syncthreads();
        s[t] += u;
        __syncthreads();
    }
    if (i < NN) g_off[i] = s[t] - v;          // exclusive local prefix
    if (t == 255) g_blksum[blockIdx.x] = s[255];
}

// Phase 2: single small block exclusive-scans the 196 block totals in-place.
__global__ void __launch_bounds__(256) k_scan2() {
    __shared__ int s[256];
    int t = threadIdx.x;
    int v = (t < SCAN_NB) ? g_blksum[t] : 0;
    s[t] = v;
    __syncthreads();
#pragma unroll
    for (int d = 1; d < 256; d <<= 1) {
        int u = (t >= d) ? s[t - d] : 0;
        __syncthreads();
        s[t] += u;
        __syncthreads();
    }
    if (t < SCAN_NB) g_blksum[t] = s[t] - v;  // exclusive
}

// Phase 3: add block offset, finalize g_off/g_cur, set sentinel.
__global__ void __launch_bounds__(256) k_scan3() {
    int t = threadIdx.x;
    int i = blockIdx.x * 256 + t;
    if (i < NN) {
        int o = g_off[i] + g_blksum[blockIdx.x];
        g_off[i] = o;
        g_cur[i] = o;
    }
    if (i == NN) g_off[NN] = EE;
}

__global__ void k_fill(const void* __restrict__ ei) {
    int e = blockIdx.x * blockDim.x + threadIdx.x;
    if (e < EE) {
        int is32 = g_is32;
        int r = load_idx(ei, e, is32);
        int c = load_idx(ei, EE + e, is32);
        int p = atomicAdd(&g_cur[r], 1);
        g_cols[p] = c;
    }
}

// ---------------- aggregate raw features: agg[n] = sum_{e: row=n} x[col_e] ----------------
__global__ void __launch_bounds__(128) k_agg(const float4* __restrict__ xv) {
    int n = blockIdx.x;
    int t = threadIdx.x;
    int beg = g_off[n], end = g_off[n + 1];
    float4 acc = make_float4(0.f, 0.f, 0.f, 0.f);
    int j = beg;
    for (; j + 3 < end; j += 4) {
        int c0 = g_cols[j], c1 = g_cols[j + 1], c2 = g_cols[j + 2], c3 = g_cols[j + 3];
        float4 v0 = xv[(size_t)c0 * 128 + t];
        float4 v1 = xv[(size_t)c1 * 128 + t];
        float4 v2 = xv[(size_t)c2 * 128 + t];
        float4 v3 = xv[(size_t)c3 * 128 + t];
        acc.x += v0.x + v1.x + v2.x + v3.x;
        acc.y += v0.y + v1.y + v2.y + v3.y;
        acc.z += v0.z + v1.z + v2.z + v3.z;
        acc.w += v0.w + v1.w + v2.w + v3.w;
    }
    for (; j < end; j++) {
        int c0 = g_cols[j];
        float4 v0 = xv[(size_t)c0 * 128 + t];
        acc.x += v0.x; acc.y += v0.y; acc.z += v0.z; acc.w += v0.w;
    }
    ((float4*)g_agg)[(size_t)n * 128 + t] = acc;
}

// ---------------- fused GEMM: out_row = [x_row | agg_row] @ [Wroot | Wrel].T (+bias) ----------------
// MODE 0: scalar rows, m -> node m, channel 0, offset m*512
// MODE 1: vector rows, m -> node m/3, channel 1+m%3
// Block tile: 128 rows x 128 outputs, K = 256 in chunks of 8. 256 threads, 8x8 micro-tile.
template <int MODE, bool BIAS>
__global__ void __launch_bounds__(256) k_gemm(const float* __restrict__ X,
                                              const float* __restrict__ Wroot,
                                              const float* __restrict__ Wrel,
                                              const float* __restrict__ bias,
                                              float* __restrict__ out, int M) {
    __shared__ float As[8][128];
    __shared__ float Bs[8][128];
    __shared__ int   roff[128];

    int tid = threadIdx.x;
    int mbase = blockIdx.x * 128;

    if (tid < 128) {
        int m = mbase + tid;
        if (m >= M) m = M - 1;          // clamp: duplicate loads, stores guarded later
        int off;
        if (MODE == 0) {
            off = m * 512;
        } else {
            int n = m / 3;
            int c = 1 + (m % 3);
            off = n * 512 + c * 128;
        }
        roff[tid] = off;
    }
    __syncthreads();

    float acc[8][8];
#pragma unroll
    for (int i = 0; i < 8; i++)
#pragma unroll
        for (int j = 0; j < 8; j++) acc[i][j] = 0.f;

    int lr  = tid >> 1;          // 0..127 : row index (A) / output index (B)
    int lkq = (tid & 1) * 4;     // 0 or 4 : which float4 of the 8-wide k-chunk

    int tm = tid >> 4;           // 0..15 -> rows tm*8..tm*8+7
    int tn = tid & 15;           // 0..15 -> cols tn*8..tn*8+7

    const float* Agg = g_agg;

#pragma unroll 1
    for (int kc = 0; kc < 32; kc++) {
        int k0 = kc * 8;
        bool first_half = (k0 < 128);
        int  kk = first_half ? k0 : (k0 - 128);
        const float* srcA = first_half ? X : Agg;
        const float* srcB = first_half ? Wroot : Wrel;

        float4 av = *(const float4*)(srcA + roff[lr] + kk + lkq);
        float4 bv = *(const float4*)(srcB + lr * 128 + kk + lkq);

        __syncthreads();   // previous chunk's compute done before overwrite
        As[lkq + 0][lr] = av.x;
        As[lkq + 1][lr] = av.y;
        As[lkq + 2][lr] = av.z;
        As[lkq + 3][lr] = av.w;
        Bs[lkq + 0][lr] = bv.x;
        Bs[lkq + 1][lr] = bv.y;
        Bs[lkq + 2][lr] = bv.z;
        Bs[lkq + 3][lr] = bv.w;
        __syncthreads();

#pragma unroll
        for (int p = 0; p < 8; p++) {
            float a[8], b[8];
            *(float4*)&a[0] = *(const float4*)&As[p][tm * 8];
            *(float4*)&a[4] = *(const float4*)&As[p][tm * 8 + 4];
            *(float4*)&b[0] = *(const float4*)&Bs[p][tn * 8];
            *(float4*)&b[4] = *(const float4*)&Bs[p][tn * 8 + 4];
#pragma unroll
            for (int i = 0; i < 8; i++)
#pragma unroll
                for (int j = 0; j < 8; j++)
                    acc[i][j] += a[i] * b[j];
        }
    }

    // epilogue
    float bs[8];
#pragma unroll
    for (int j = 0; j < 8; j++) bs[j] = BIAS ? bias[tn * 8 + j] : 0.f;

#pragma unroll
    for (int i = 0; i < 8; i++) {
        int lm = tm * 8 + i;
        int m  = mbase + lm;
        if (m < M) {
            float* o = out + roff[lm] + tn * 8;
            float4 v0, v1;
            v0.x = acc[i][0] + bs[0]; v0.y = acc[i][1] + bs[1];
            v0.z = acc[i][2] + bs[2]; v0.w = acc[i][3] + bs[3];
            v1.x = acc[i][4] + bs[4]; v1.y = acc[i][5] + bs[5];
            v1.z = acc[i][6] + bs[6]; v1.w = acc[i][7] + bs[7];
            *(float4*)(o)     = v0;
            *(float4*)(o + 4) = v1;
        }
    }
}

extern "C" void kernel_launch(void* const* d_in, const int* in_sizes, int n_in,
                              void* d_out, int out_size) {
    const float* x        = (const float*)d_in[0];
    const void*  ei       = d_in[1];
    const float* W_s_rel  = (const float*)d_in[2];
    const float* W_s_root = (const float*)d_in[3];
    const float* b_s_root = (const float*)d_in[4];
    const float* W_v_rel  = (const float*)d_in[5];
    const float* W_v_root = (const float*)d_in[6];
    float*       out      = (float*)d_out;

    k_init<<<(NN + 255) / 256, 256>>>();
    k_dtype_detect<<<(EE + 255) / 256, 256>>>((const long long*)ei);
    k_hist<<<(EE + 255) / 256, 256>>>(ei);
    k_scan1<<<SCAN_NB, 256>>>();
    k_scan2<<<1, 256>>>();
    k_scan3<<<SCAN_NB + 1, 256>>>();   // +1 block so i==NN sentinel is covered
    k_fill<<<(EE + 255) / 256, 256>>>(ei);
    k_agg<<<NN, 128>>>((const float4*)x);

    // scalar channel: out[:,0,:] = x_s @ Ws_root.T + b + agg_s @ Ws_rel.T
    k_gemm<0, true><<<(NN + 127) / 128, 256>>>(x, W_s_root, W_s_rel, b_s_root, out, NN);
    // vector channels: out[:,1:,:] = x_v @ Wv_root.T + agg_v @ Wv_rel.T
    k_gemm<1, false><<<(3 * NN + 127) / 128, 256>>>(x, W_v_root, W_v_rel, nullptr, out, 3 * NN);
}

// round 10
// speedup vs baseline: 2.0932x; 1.7116x over previous
#include <cuda_runtime.h>
#include <cstdint>

#define NN 50000
#define EE 500000
#define HH 128
#define SCAN_NB 196   // ceil(50000/256)

// ---- scratch (static __device__ arrays; no runtime allocation) ----
__device__ int   g_cnt[NN];
__device__ int   g_off[NN + 1];
__device__ int   g_cur[NN];
__device__ int   g_cols[EE];
__device__ int   g_blksum[SCAN_NB];
__device__ int   g_is32;                    // 1 if edge_index buffer is int32
__device__ float g_agg[(size_t)NN * 512];   // aggregated raw features, layout == x

// ================= warp-mma helpers (sm_80+ PTX, valid for compute_103) =========
__device__ __forceinline__ uint32_t smem_u32(const void* p) {
    uint32_t a;
    asm("{ .reg .u64 t; cvta.to.shared.u64 t, %1; cvt.u32.u64 %0, t; }" : "=r"(a) : "l"(p));
    return a;
}
__device__ __forceinline__ void ldsm_x4(uint32_t* r, uint32_t addr) {
    asm volatile("ldmatrix.sync.aligned.m8n8.x4.shared.b16 {%0,%1,%2,%3}, [%4];"
                 : "=r"(r[0]), "=r"(r[1]), "=r"(r[2]), "=r"(r[3]) : "r"(addr));
}
__device__ __forceinline__ void ldsm_x2(uint32_t* r, uint32_t addr) {
    asm volatile("ldmatrix.sync.aligned.m8n8.x2.shared.b16 {%0,%1}, [%2];"
                 : "=r"(r[0]), "=r"(r[1]) : "r"(addr));
}
__device__ __forceinline__ void mma_bf16(float* c, const uint32_t* a, const uint32_t* b) {
    asm volatile("mma.sync.aligned.m16n8k16.row.col.f32.bf16.bf16.f32 "
                 "{%0,%1,%2,%3}, {%4,%5,%6,%7}, {%8,%9}, {%0,%1,%2,%3};"
                 : "+f"(c[0]), "+f"(c[1]), "+f"(c[2]), "+f"(c[3])
                 : "r"(a[0]), "r"(a[1]), "r"(a[2]), "r"(a[3]), "r"(b[0]), "r"(b[1]));
}
// pack (lo_el -> low16, hi_el -> high16) as bf16x2
__device__ __forceinline__ uint32_t pack_bf16x2(float hi_el, float lo_el) {
    uint32_t r;
    asm("cvt.rn.bf16x2.f32 %0, %1, %2;" : "=r"(r) : "f"(hi_el), "f"(lo_el));
    return r;
}

// ---------------- dtype detection + zero (fused) ----------------
__global__ void k_init() {
    int i = blockIdx.x * blockDim.x + threadIdx.x;
    if (i == 0) g_is32 = 0;
    if (i < NN) g_cnt[i] = 0;
}

__global__ void k_dtype_detect(const long long* __restrict__ ei) {
    int e = blockIdx.x * blockDim.x + threadIdx.x;
    if (e < EE) {
        long long v = ei[e];
        if (v < 0 || v >= NN) atomicOr(&g_is32, 1);
    }
}

__device__ __forceinline__ int load_idx(const void* ei, int pos, int is32) {
    long long v;
    if (is32) v = ((const int*)ei)[pos];
    else      v = ((const long long*)ei)[pos];
    int r = (int)v;
    if (r < 0) r = 0;
    if (r >= NN) r = NN - 1;
    return r;
}

// ---------------- CSR build ----------------
__global__ void k_hist(const void* __restrict__ ei) {
    int e = blockIdx.x * blockDim.x + threadIdx.x;
    if (e < EE) {
        int is32 = g_is32;
        int r = load_idx(ei, e, is32);
        atomicAdd(&g_cnt[r], 1);
    }
}

__global__ void __launch_bounds__(256) k_scan1() {
    __shared__ int s[256];
    int t = threadIdx.x;
    int i = blockIdx.x * 256 + t;
    int v = (i < NN) ? g_cnt[i] : 0;
    s[t] = v;
    __syncthreads();
#pragma unroll
    for (int d = 1; d < 256; d <<= 1) {
        int u = (t >= d) ? s[t - d] : 0;
        __syncthreads();
        s[t] += u;
        __syncthreads();
    }
    if (i < NN) g_off[i] = s[t] - v;
    if (t == 255) g_blksum[blockIdx.x] = s[255];
}

__global__ void __launch_bounds__(256) k_scan2() {
    __shared__ int s[256];
    int t = threadIdx.x;
    int v = (t < SCAN_NB) ? g_blksum[t] : 0;
    s[t] = v;
    __syncthreads();
#pragma unroll
    for (int d = 1; d < 256; d <<= 1) {
        int u = (t >= d) ? s[t - d] : 0;
        __syncthreads();
        s[t] += u;
        __syncthreads();
    }
    if (t < SCAN_NB) g_blksum[t] = s[t] - v;
}

__global__ void __launch_bounds__(256) k_scan3() {
    int t = threadIdx.x;
    int i = blockIdx.x * 256 + t;
    if (i < NN) {
        int o = g_off[i] + g_blksum[blockIdx.x];
        g_off[i] = o;
        g_cur[i] = o;
    }
    if (i == NN) g_off[NN] = EE;
}

__global__ void k_fill(const void* __restrict__ ei) {
    int e = blockIdx.x * blockDim.x + threadIdx.x;
    if (e < EE) {
        int is32 = g_is32;
        int r = load_idx(ei, e, is32);
        int c = load_idx(ei, EE + e, is32);
        int p = atomicAdd(&g_cur[r], 1);
        g_cols[p] = c;
    }
}

// ---------------- aggregate raw features: agg[n] = sum_{e: row=n} x[col_e] ----------------
__global__ void __launch_bounds__(128) k_agg(const float4* __restrict__ xv) {
    int n = blockIdx.x;
    int t = threadIdx.x;
    int beg = g_off[n], end = g_off[n + 1];
    float4 acc = make_float4(0.f, 0.f, 0.f, 0.f);
    int j = beg;
    for (; j + 3 < end; j += 4) {
        int c0 = g_cols[j], c1 = g_cols[j + 1], c2 = g_cols[j + 2], c3 = g_cols[j + 3];
        float4 v0 = xv[(size_t)c0 * 128 + t];
        float4 v1 = xv[(size_t)c1 * 128 + t];
        float4 v2 = xv[(size_t)c2 * 128 + t];
        float4 v3 = xv[(size_t)c3 * 128 + t];
        acc.x += v0.x + v1.x + v2.x + v3.x;
        acc.y += v0.y + v1.y + v2.y + v3.y;
        acc.z += v0.z + v1.z + v2.z + v3.z;
        acc.w += v0.w + v1.w + v2.w + v3.w;
    }
    for (; j < end; j++) {
        int c0 = g_cols[j];
        float4 v0 = xv[(size_t)c0 * 128 + t];
        acc.x += v0.x; acc.y += v0.y; acc.z += v0.z; acc.w += v0.w;
    }
    ((float4*)g_agg)[(size_t)n * 128 + t] = acc;
}

// ---------------- 3xBF16 mma.sync GEMM ----------------
// out_row = [x_row | agg_row] (K=256) @ [Wroot | Wrel].T (+bias)
// One 256-thread block computes a 128x128 output tile. 8 warps in 4x2 layout:
// warp tile 32 rows x 64 cols, m16n8k16 fragments, 3-term bf16 split precision.
// K processed in 8 chunks of 32; fp32->bf16 hi/lo split done in registers,
// staged to padded smem tiles (stride 80B), read back via ldmatrix.

#define TSTRIDE 80                      // bytes per 32-bf16 row (64 + 16 pad)
#define SM_ROFF 0                       // int[128]
#define SM_AHI  512
#define SM_ALO  (512 + 10240)
#define SM_BHI  (512 + 20480)
#define SM_BLO  (512 + 30720)
#define SM_TOT  (512 + 40960)

template <int MODE, bool BIAS>
__global__ void __launch_bounds__(256) k_mgemm(const float* __restrict__ X,
                                               const float* __restrict__ Wroot,
                                               const float* __restrict__ Wrel,
                                               const float* __restrict__ bias,
                                               float* __restrict__ out, int M) {
    __shared__ __align__(16) char sm[SM_TOT];
    int* roff_s = (int*)(sm + SM_ROFF);
    uint32_t sbase = smem_u32(sm);

    int tid = threadIdx.x;
    int lane = tid & 31;
    int wid = tid >> 5;
    int mbase = blockIdx.x * 128;

    if (tid < 128) {
        int m = mbase + tid;
        if (m >= M) m = M - 1;          // clamp: duplicate loads, stores guarded
        int off;
        if (MODE == 0) off = m * 512;
        else { int n = m / 3; int c = 1 + (m % 3); off = n * 512 + c * 128; }
        roff_s[tid] = off;
    }
    __syncthreads();

    // --- load/convert role: thread handles one row (A) + one weight row (B),
    //     16 floats each per chunk ---
    int lrow = tid >> 1;                 // 0..127
    int khf  = (tid & 1) * 16;           // float offset within 32-wide chunk
    int arow = roff_s[lrow];
    uint32_t st_off = (uint32_t)lrow * TSTRIDE + (uint32_t)khf * 2;  // bytes

    // --- compute role: warp tiling ---
    int warpM = wid & 3;                 // 0..3 -> 32-row slabs
    int warpN = wid >> 2;                // 0..1 -> 64-col slabs
    int g  = lane >> 3;                  // ldmatrix lane group
    int rr = lane & 7;
    uint32_t aoff0 = (uint32_t)(warpM * 32 + 0  + rr + (g & 1) * 8) * TSTRIDE + (g >> 1) * 16;
    uint32_t aoff1 = (uint32_t)(warpM * 32 + 16 + rr + (g & 1) * 8) * TSTRIDE + (g >> 1) * 16;
    uint32_t boff  = (uint32_t)(warpN * 64 + rr) * TSTRIDE + ((lane >> 3) & 1) * 16;

    float acc[2][8][4];
#pragma unroll
    for (int mt = 0; mt < 2; mt++)
#pragma unroll
        for (int nt = 0; nt < 8; nt++)
#pragma unroll
            for (int q = 0; q < 4; q++) acc[mt][nt][q] = 0.f;

    const float* Agg = g_agg;

#pragma unroll 1
    for (int c = 0; c < 8; c++) {
        bool fh = (c < 4);
        int koff = (c & 3) * 32;
        const float* pa = (fh ? X : Agg) + arow + koff + khf;
        const float* pb = (fh ? Wroot : Wrel) + lrow * 128 + koff + khf;

        // load 16+16 floats, split to bf16 hi/lo in registers
        uint2 ahi[4], alo[4], bhi[4], blo[4];
#pragma unroll
        for (int q = 0; q < 4; q++) {
            float4 f = ((const float4*)pa)[q];
            uint32_t ux = __float_as_uint(f.x), uy = __float_as_uint(f.y);
            uint32_t uz = __float_as_uint(f.z), uw = __float_as_uint(f.w);
            ahi[q].x = __byte_perm(ux, uy, 0x7632);
            ahi[q].y = __byte_perm(uz, uw, 0x7632);
            float lx = f.x - __uint_as_float(ux & 0xFFFF0000u);
            float ly = f.y - __uint_as_float(uy & 0xFFFF0000u);
            float lz = f.z - __uint_as_float(uz & 0xFFFF0000u);
            float lw = f.w - __uint_as_float(uw & 0xFFFF0000u);
            alo[q].x = pack_bf16x2(ly, lx);
            alo[q].y = pack_bf16x2(lw, lz);
        }
#pragma unroll
        for (int q = 0; q < 4; q++) {
            float4 f = ((const float4*)pb)[q];
            uint32_t ux = __float_as_uint(f.x), uy = __float_as_uint(f.y);
            uint32_t uz = __float_as_uint(f.z), uw = __float_as_uint(f.w);
            bhi[q].x = __byte_perm(ux, uy, 0x7632);
            bhi[q].y = __byte_perm(uz, uw, 0x7632);
            float lx = f.x - __uint_as_float(ux & 0xFFFF0000u);
            float ly = f.y - __uint_as_float(uy & 0xFFFF0000u);
            float lz = f.z - __uint_as_float(uz & 0xFFFF0000u);
            float lw = f.w - __uint_as_float(uw & 0xFFFF0000u);
            blo[q].x = pack_bf16x2(ly, lx);
            blo[q].y = pack_bf16x2(lw, lz);
        }

        __syncthreads();   // previous chunk's compute done reading tiles
#pragma unroll
        for (int q = 0; q < 4; q++) {
            *(uint2*)(sm + SM_AHI + st_off + q * 8) = ahi[q];
            *(uint2*)(sm + SM_ALO + st_off + q * 8) = alo[q];
            *(uint2*)(sm + SM_BHI + st_off + q * 8) = bhi[q];
            *(uint2*)(sm + SM_BLO + st_off + q * 8) = blo[q];
        }
        __syncthreads();

        // compute: 2 k16 steps
#pragma unroll
        for (int ks = 0; ks < 2; ks++) {
            uint32_t a0h[4], a0l[4], a1h[4], a1l[4];
            ldsm_x4(a0h, sbase + SM_AHI + aoff0 + ks * 32);
            ldsm_x4(a0l, sbase + SM_ALO + aoff0 + ks * 32);
            ldsm_x4(a1h, sbase + SM_AHI + aoff1 + ks * 32);
            ldsm_x4(a1l, sbase + SM_ALO + aoff1 + ks * 32);
#pragma unroll
            for (int nt = 0; nt < 8; nt++) {
                uint32_t bh[2], bl[2];
                ldsm_x2(bh, sbase + SM_BHI + boff + nt * (8 * TSTRIDE) + ks * 32);
                ldsm_x2(bl, sbase + SM_BLO + boff + nt * (8 * TSTRIDE) + ks * 32);
                mma_bf16(acc[0][nt], a0h, bh);
                mma_bf16(acc[0][nt], a0l, bh);
                mma_bf16(acc[0][nt], a0h, bl);
                mma_bf16(acc[1][nt], a1h, bh);
                mma_bf16(acc[1][nt], a1l, bh);
                mma_bf16(acc[1][nt], a1h, bl);
            }
        }
    }

    // epilogue: c0,c1 -> (row = base + lane/4, col, col+1); c2,c3 -> row+8
#pragma unroll
    for (int mt = 0; mt < 2; mt++) {
        int lr0 = warpM * 32 + mt * 16 + (lane >> 2);
        int lr1 = lr0 + 8;
        bool live0 = (mbase + lr0) < M;
        bool live1 = (mbase + lr1) < M;
        int o0 = roff_s[lr0];
        int o1 = roff_s[lr1];
#pragma unroll
        for (int nt = 0; nt < 8; nt++) {
            int col = warpN * 64 + nt * 8 + 2 * (lane & 3);
            float b0 = 0.f, b1 = 0.f;
            if (BIAS) { b0 = bias[col]; b1 = bias[col + 1]; }
            if (live0) {
                float2 v = make_float2(acc[mt][nt][0] + b0, acc[mt][nt][1] + b1);
                *(float2*)(out + o0 + col) = v;
            }
            if (live1) {
                float2 v = make_float2(acc[mt][nt][2] + b0, acc[mt][nt][3] + b1);
                *(float2*)(out + o1 + col) = v;
            }
        }
    }
}

extern "C" void kernel_launch(void* const* d_in, const int* in_sizes, int n_in,
                              void* d_out, int out_size) {
    const float* x        = (const float*)d_in[0];
    const void*  ei       = d_in[1];
    const float* W_s_rel  = (const float*)d_in[2];
    const float* W_s_root = (const float*)d_in[3];
    const float* b_s_root = (const float*)d_in[4];
    const float* W_v_rel  = (const float*)d_in[5];
    const float* W_v_root = (const float*)d_in[6];
    float*       out      = (float*)d_out;

    k_init<<<(NN + 255) / 256, 256>>>();
    k_dtype_detect<<<(EE + 255) / 256, 256>>>((const long long*)ei);
    k_hist<<<(EE + 255) / 256, 256>>>(ei);
    k_scan1<<<SCAN_NB, 256>>>();
    k_scan2<<<1, 256>>>();
    k_scan3<<<SCAN_NB + 1, 256>>>();
    k_fill<<<(EE + 255) / 256, 256>>>(ei);
    k_agg<<<NN, 128>>>((const float4*)x);

    // scalar channel: out[:,0,:] = x_s @ Ws_root.T + b + agg_s @ Ws_rel.T
    k_mgemm<0, true><<<(NN + 127) / 128, 256>>>(x, W_s_root, W_s_rel, b_s_root, out, NN);
    // vector channels: out[:,1:,:] = x_v @ Wv_root.T + agg_v @ Wv_rel.T
    k_mgemm<1, false><<<(3 * NN + 127) / 128, 256>>>(x, W_v_root, W_v_rel, nullptr, out, 3 * NN);
}